// round 9
// baseline (speedup 1.0000x reference)
#include <cuda_runtime.h>
#include <cuda_fp16.h>
#include <cstdint>

#define OUTD 11008
#define IND  4096
#define BDIM 8192
#define NELEM (OUTD * IND)
#define PPACK (NELEM / 2)
#define XELEM (BDIM * IND)

__device__ __half g_W[NELEM];
__device__ __half g_X[XELEM];

// ---------------------------------------------------------------------------
// Kernel 0: x f32 -> fp16 (lossless)
// ---------------------------------------------------------------------------
__global__ void __launch_bounds__(256) xconv_kernel(const float* __restrict__ x)
{
    int tid = blockIdx.x * 256 + threadIdx.x;
    const float4* x4 = (const float4*)x;
    float4 a = x4[tid * 2];
    float4 b = x4[tid * 2 + 1];
    __half h[8];
    h[0] = __float2half(a.x); h[1] = __float2half(a.y);
    h[2] = __float2half(a.z); h[3] = __float2half(a.w);
    h[4] = __float2half(b.x); h[5] = __float2half(b.y);
    h[6] = __float2half(b.z); h[7] = __float2half(b.w);
    ((uint4*)g_X)[tid] = *(const uint4*)h;
}

// ---------------------------------------------------------------------------
// Kernel 1: dequant 4-bit -> fp16 W (verified)
// ---------------------------------------------------------------------------
__global__ void __launch_bounds__(256) dequant_kernel(
    const int*   __restrict__ packed,
    const int*   __restrict__ absmax1,
    const float* __restrict__ code1,
    const float* __restrict__ offset1,
    const float* __restrict__ absmax2,
    const float* __restrict__ code2)
{
    int tid = blockIdx.x * 256 + threadIdx.x;
    int blk1 = tid >> 2;
    int blk2 = tid >> 4;
    float s   = ((float)absmax1[blk1] / code1[blk1]) * (absmax2[blk2] / code2[blk2]);
    float off = offset1[blk1];
    const int4* p4 = (const int4*)packed;
    int4 p0 = p4[tid * 2];
    int4 p1 = p4[tid * 2 + 1];
    int b[8] = {p0.x, p0.y, p0.z, p0.w, p1.x, p1.y, p1.z, p1.w};
    __half h[16];
#pragma unroll
    for (int j = 0; j < 8; j++) {
        float lo = (float)(b[j] & 15);
        float hi = (float)((b[j] >> 4) & 15);
        h[2 * j]     = __float2half((lo - off) * s);
        h[2 * j + 1] = __float2half((hi - off) * s);
    }
    uint4* w4 = (uint4*)g_W;
    const uint4* hv = (const uint4*)h;
    w4[tid * 2]     = hv[0];
    w4[tid * 2 + 1] = hv[1];
}

// ---------------------------------------------------------------------------
// Kernel 2: HMMA GEMM. BM=128, BN=256, BK=64; 512 threads = 16 warps 4(M)x4(N);
// warp tile 32x64 (same as R5); 3-stage cp.async ring; L2 traffic -25% vs R5.
// ---------------------------------------------------------------------------
#define BM 128
#define BN 256
#define BK 64
#define STAGES 3
#define KTILES (IND / BK)            // 64
#define A_STG 16384                  // 128 rows x 128 B
#define B_STG 32768                  // 256 rows x 128 B
#define SMEM_TOTAL (STAGES * (A_STG + B_STG))   // 147456

__device__ __forceinline__ unsigned swz(int row, int kc) {
    return (unsigned)(row * 128 + ((kc ^ (row & 7)) << 4));
}
__device__ __forceinline__ void ldm_x4(unsigned* d, unsigned addr) {
    asm volatile("ldmatrix.sync.aligned.m8n8.x4.shared.b16 {%0,%1,%2,%3}, [%4];"
                 : "=r"(d[0]), "=r"(d[1]), "=r"(d[2]), "=r"(d[3]) : "r"(addr));
}
__device__ __forceinline__ void mma16816(float* c, const unsigned* a,
                                         unsigned b0, unsigned b1) {
    asm volatile(
        "mma.sync.aligned.m16n8k16.row.col.f32.f16.f16.f32 "
        "{%0,%1,%2,%3}, {%4,%5,%6,%7}, {%8,%9}, {%0,%1,%2,%3};"
        : "+f"(c[0]), "+f"(c[1]), "+f"(c[2]), "+f"(c[3])
        : "r"(a[0]), "r"(a[1]), "r"(a[2]), "r"(a[3]), "r"(b0), "r"(b1));
}
__device__ __forceinline__ void cp_async16(unsigned saddr, const void* gaddr) {
    asm volatile("cp.async.cg.shared.global [%0], [%1], 16;"
                 :: "r"(saddr), "l"(gaddr));
}

__global__ void __launch_bounds__(512, 1) gemm_kernel(float* __restrict__ C)
{
    extern __shared__ char smem[];
    unsigned sA = (unsigned)__cvta_generic_to_shared(smem);       // 3 x 16KB
    unsigned sB = sA + STAGES * A_STG;                            // 3 x 32KB

    const int tid  = threadIdx.x;
    const int lane = tid & 31;
    const int warp = tid >> 5;      // 0..15
    const int wm   = warp >> 2;     // 0..3 (M)
    const int wn   = warp & 3;      // 0..3 (N)

    const int bn = blockIdx.x;      // 0..42
    const int bm = blockIdx.y;      // 0..63

    const __half* xsrc0 = g_X + (size_t)bm * BM * IND;
    const __half* wsrc0 = g_W + (size_t)bn * BN * IND;

    float acc[2][8][4] = {};

    const int rselA = lane & 15;
    const int cselA = lane >> 4;
    const int rselB = (lane & 7) | ((lane >> 1) & 8);
    const int cselB = (lane >> 3) & 1;

    unsigned aRowOff[2]; int aXor[2];
#pragma unroll
    for (int mi = 0; mi < 2; mi++) {
        int r = wm * 32 + mi * 16 + rselA;
        aRowOff[mi] = (unsigned)(r * 128);
        aXor[mi] = r & 7;
    }
    unsigned bRowOff[4]; int bXor[4];
#pragma unroll
    for (int nj = 0; nj < 4; nj++) {
        int r = wn * 64 + nj * 16 + rselB;
        bRowOff[nj] = (unsigned)(r * 128);
        bXor[nj] = r & 7;
    }

    auto load_stage = [&](int slot, int kt) {
        unsigned aB = sA + slot * A_STG;
        unsigned bB = sB + slot * B_STG;
        const __half* xs = xsrc0 + (size_t)kt * BK;
        const __half* ws = wsrc0 + (size_t)kt * BK;
#pragma unroll
        for (int i = 0; i < 2; i++) {                 // A: 1024 chunks / 512 thr
            int id = tid + i * 512;
            int row = id >> 3, kc = id & 7;
            cp_async16(aB + swz(row, kc), xs + (size_t)row * IND + kc * 8);
        }
#pragma unroll
        for (int i = 0; i < 4; i++) {                 // B: 2048 chunks / 512 thr
            int id = tid + i * 512;
            int row = id >> 3, kc = id & 7;
            cp_async16(bB + swz(row, kc), ws + (size_t)row * IND + kc * 8);
        }
    };

    load_stage(0, 0);
    asm volatile("cp.async.commit_group;");
    load_stage(1, 1);
    asm volatile("cp.async.commit_group;");

    for (int kt = 0; kt < KTILES; kt++) {
        asm volatile("cp.async.wait_group 1;");       // stage kt resident
        __syncthreads();                              // all warps done with kt-1

        if (kt + 2 < KTILES) load_stage((kt + 2) % STAGES, kt + 2);
        asm volatile("cp.async.commit_group;");

        unsigned aBase = sA + (kt % STAGES) * A_STG;
        unsigned bBase = sB + (kt % STAGES) * B_STG;
#pragma unroll
        for (int kk = 0; kk < 4; kk++) {
            unsigned afrag[2][4];
#pragma unroll
            for (int mi = 0; mi < 2; mi++) {
                int kc = kk * 2 + cselA;
                ldm_x4(afrag[mi], aBase + aRowOff[mi] + (unsigned)((kc ^ aXor[mi]) << 4));
            }
            unsigned bfrag[4][4];
#pragma unroll
            for (int nj = 0; nj < 4; nj++) {
                int kc = kk * 2 + cselB;
                ldm_x4(bfrag[nj], bBase + bRowOff[nj] + (unsigned)((kc ^ bXor[nj]) << 4));
            }
#pragma unroll
            for (int mi = 0; mi < 2; mi++) {
#pragma unroll
                for (int nj = 0; nj < 4; nj++) {
                    mma16816(acc[mi][2 * nj],     afrag[mi], bfrag[nj][0], bfrag[nj][1]);
                    mma16816(acc[mi][2 * nj + 1], afrag[mi], bfrag[nj][2], bfrag[nj][3]);
                }
            }
        }
    }

    // ---- epilogue: fp16-round, store f32 ----
    const int r0 = bm * BM + wm * 32 + (lane >> 2);
    const int c0 = bn * BN + wn * 64 + 2 * (lane & 3);
#pragma unroll
    for (int mi = 0; mi < 2; mi++) {
#pragma unroll
        for (int ni = 0; ni < 8; ni++) {
            int r = r0 + mi * 16;
            int c = c0 + ni * 8;
            float2 v0 = make_float2(__half2float(__float2half(acc[mi][ni][0])),
                                    __half2float(__float2half(acc[mi][ni][1])));
            float2 v1 = make_float2(__half2float(__float2half(acc[mi][ni][2])),
                                    __half2float(__float2half(acc[mi][ni][3])));
            *(float2*)(C + (size_t)r * OUTD + c)       = v0;
            *(float2*)(C + (size_t)(r + 8) * OUTD + c) = v1;
        }
    }
}

// ---------------------------------------------------------------------------
extern "C" void kernel_launch(void* const* d_in, const int* in_sizes, int n_in,
                              void* d_out, int out_size)
{
    const float* x      = (const float*)d_in[0];
    const int*   packed = (const int*)  d_in[1];
    const int*   am1    = (const int*)  d_in[2];
    const float* c1     = (const float*)d_in[3];
    const float* o1     = (const float*)d_in[4];
    const float* am2    = (const float*)d_in[5];
    const float* c2     = (const float*)d_in[6];
    float* out = (float*)d_out;

    xconv_kernel<<<XELEM / 8 / 256, 256>>>(x);
    dequant_kernel<<<PPACK / 8 / 256, 256>>>(packed, am1, c1, o1, am2, c2);

    cudaFuncSetAttribute(gemm_kernel,
                         cudaFuncAttributeMaxDynamicSharedMemorySize, SMEM_TOTAL);
    gemm_kernel<<<dim3(OUTD / BN, BDIM / BM), 512, SMEM_TOTAL>>>(out);
}

// round 11
// speedup vs baseline: 1.0853x; 1.0853x over previous
#include <cuda_runtime.h>
#include <cuda_fp16.h>
#include <cstdint>

#define OUTD 11008
#define IND  4096
#define BDIM 8192
#define NELEM (OUTD * IND)
#define PPACK (NELEM / 2)
#define XELEM (BDIM * IND)

__device__ __half g_W[NELEM];
__device__ __half g_X[XELEM];

// ---------------------------------------------------------------------------
// Kernel P: fused prep. Blocks [0, XBLK) convert x f32->fp16; the rest
// dequantize packed 4-bit -> fp16 W. Both HBM-bound; one grid keeps HBM full.
// ---------------------------------------------------------------------------
#define XBLK (XELEM / 8 / 256)        // 16384
#define DQBLK (PPACK / 8 / 256)       // 11008

__global__ void __launch_bounds__(256) prep_kernel(
    const float* __restrict__ x,
    const int*   __restrict__ packed,
    const int*   __restrict__ absmax1,
    const float* __restrict__ code1,
    const float* __restrict__ offset1,
    const float* __restrict__ absmax2,
    const float* __restrict__ code2)
{
    if (blockIdx.x < XBLK) {
        int tid = blockIdx.x * 256 + threadIdx.x;
        const float4* x4 = (const float4*)x;
        float4 a = x4[tid * 2];
        float4 b = x4[tid * 2 + 1];
        __half h[8];
        h[0] = __float2half(a.x); h[1] = __float2half(a.y);
        h[2] = __float2half(a.z); h[3] = __float2half(a.w);
        h[4] = __float2half(b.x); h[5] = __float2half(b.y);
        h[6] = __float2half(b.z); h[7] = __float2half(b.w);
        ((uint4*)g_X)[tid] = *(const uint4*)h;
    } else {
        int tid = (blockIdx.x - XBLK) * 256 + threadIdx.x;   // [0, PPACK/8)
        int blk1 = tid >> 2;
        int blk2 = tid >> 4;
        float s   = ((float)absmax1[blk1] / code1[blk1]) * (absmax2[blk2] / code2[blk2]);
        float off = offset1[blk1];
        const int4* p4 = (const int4*)packed;
        int4 p0 = p4[tid * 2];
        int4 p1 = p4[tid * 2 + 1];
        int b[8] = {p0.x, p0.y, p0.z, p0.w, p1.x, p1.y, p1.z, p1.w};
        __half h[16];
#pragma unroll
        for (int j = 0; j < 8; j++) {
            float lo = (float)(b[j] & 15);
            float hi = (float)((b[j] >> 4) & 15);
            h[2 * j]     = __float2half((lo - off) * s);
            h[2 * j + 1] = __float2half((hi - off) * s);
        }
        uint4* w4 = (uint4*)g_W;
        const uint4* hv = (const uint4*)h;
        w4[tid * 2]     = hv[0];
        w4[tid * 2 + 1] = hv[1];
    }
}

// ---------------------------------------------------------------------------
// Kernel 2: HMMA GEMM — R5 configuration, verbatim mainloop.
// BM=128, BN=128, BK=64; 8 warps 4(M)x2(N), warp tile 32x64; 3-stage ring;
// 2 CTAs/SM. Epilogue uses streaming stores (evict-first) to preserve L2.
// ---------------------------------------------------------------------------
#define BM 128
#define BN 128
#define BK 64
#define STAGES 3
#define KTILES (IND / BK)            // 64
#define STG_BYTES 16384
#define SMEM_TOTAL (2 * STAGES * STG_BYTES)   // 98304

__device__ __forceinline__ unsigned swz(int row, int kc) {
    return (unsigned)(row * 128 + ((kc ^ (row & 7)) << 4));
}
__device__ __forceinline__ void ldm_x4(unsigned* d, unsigned addr) {
    asm volatile("ldmatrix.sync.aligned.m8n8.x4.shared.b16 {%0,%1,%2,%3}, [%4];"
                 : "=r"(d[0]), "=r"(d[1]), "=r"(d[2]), "=r"(d[3]) : "r"(addr));
}
__device__ __forceinline__ void mma16816(float* c, const unsigned* a,
                                         unsigned b0, unsigned b1) {
    asm volatile(
        "mma.sync.aligned.m16n8k16.row.col.f32.f16.f16.f32 "
        "{%0,%1,%2,%3}, {%4,%5,%6,%7}, {%8,%9}, {%0,%1,%2,%3};"
        : "+f"(c[0]), "+f"(c[1]), "+f"(c[2]), "+f"(c[3])
        : "r"(a[0]), "r"(a[1]), "r"(a[2]), "r"(a[3]), "r"(b0), "r"(b1));
}
__device__ __forceinline__ void cp_async16(unsigned saddr, const void* gaddr) {
    asm volatile("cp.async.cg.shared.global [%0], [%1], 16;"
                 :: "r"(saddr), "l"(gaddr));
}
__device__ __forceinline__ void stcs2(float* p, float a, float b) {
    asm volatile("st.global.cs.v2.f32 [%0], {%1, %2};" :: "l"(p), "f"(a), "f"(b)
                 : "memory");
}

__global__ void __launch_bounds__(256, 2) gemm_kernel(float* __restrict__ C)
{
    extern __shared__ char smem[];
    unsigned sA = (unsigned)__cvta_generic_to_shared(smem);
    unsigned sB = sA + STAGES * STG_BYTES;

    const int tid  = threadIdx.x;
    const int lane = tid & 31;
    const int warp = tid >> 5;
    const int wm   = warp >> 1;     // 0..3
    const int wn   = warp & 1;      // 0..1

    const int bn = blockIdx.x;
    const int bm = blockIdx.y;

    const __half* xsrc0 = g_X + (size_t)bm * BM * IND;
    const __half* wsrc0 = g_W + (size_t)bn * BN * IND;

    float acc[2][8][4] = {};

    const int rselA = lane & 15;
    const int cselA = lane >> 4;
    const int rselB = (lane & 7) | ((lane >> 1) & 8);
    const int cselB = (lane >> 3) & 1;

    unsigned aRowOff[2]; int aXor[2];
#pragma unroll
    for (int mi = 0; mi < 2; mi++) {
        int r = wm * 32 + mi * 16 + rselA;
        aRowOff[mi] = (unsigned)(r * 128);
        aXor[mi] = r & 7;
    }
    unsigned bRowOff[4]; int bXor[4];
#pragma unroll
    for (int nj = 0; nj < 4; nj++) {
        int r = wn * 64 + nj * 16 + rselB;
        bRowOff[nj] = (unsigned)(r * 128);
        bXor[nj] = r & 7;
    }

    auto load_stage = [&](int slot, int kt) {
        unsigned aB = sA + slot * STG_BYTES;
        unsigned bB = sB + slot * STG_BYTES;
        const __half* xs = xsrc0 + (size_t)kt * BK;
        const __half* ws = wsrc0 + (size_t)kt * BK;
#pragma unroll
        for (int i = 0; i < 4; i++) {
            int id = tid + i * 256;
            int row = id >> 3, kc = id & 7;
            cp_async16(aB + swz(row, kc), xs + (size_t)row * IND + kc * 8);
        }
#pragma unroll
        for (int i = 0; i < 4; i++) {
            int id = tid + i * 256;
            int row = id >> 3, kc = id & 7;
            cp_async16(bB + swz(row, kc), ws + (size_t)row * IND + kc * 8);
        }
    };

    load_stage(0, 0);
    asm volatile("cp.async.commit_group;");
    load_stage(1, 1);
    asm volatile("cp.async.commit_group;");

    for (int kt = 0; kt < KTILES; kt++) {
        asm volatile("cp.async.wait_group 1;");   // stage kt resident
        __syncthreads();                          // all warps done with kt-1

        if (kt + 2 < KTILES) load_stage((kt + 2) % STAGES, kt + 2);
        asm volatile("cp.async.commit_group;");

        unsigned aBase = sA + (kt % STAGES) * STG_BYTES;
        unsigned bBase = sB + (kt % STAGES) * STG_BYTES;
#pragma unroll
        for (int kk = 0; kk < 4; kk++) {
            unsigned afrag[2][4];
#pragma unroll
            for (int mi = 0; mi < 2; mi++) {
                int kc = kk * 2 + cselA;
                ldm_x4(afrag[mi], aBase + aRowOff[mi] + (unsigned)((kc ^ aXor[mi]) << 4));
            }
            unsigned bfrag[4][4];
#pragma unroll
            for (int nj = 0; nj < 4; nj++) {
                int kc = kk * 2 + cselB;
                ldm_x4(bfrag[nj], bBase + bRowOff[nj] + (unsigned)((kc ^ bXor[nj]) << 4));
            }
#pragma unroll
            for (int mi = 0; mi < 2; mi++) {
#pragma unroll
                for (int nj = 0; nj < 4; nj++) {
                    mma16816(acc[mi][2 * nj],     afrag[mi], bfrag[nj][0], bfrag[nj][1]);
                    mma16816(acc[mi][2 * nj + 1], afrag[mi], bfrag[nj][2], bfrag[nj][3]);
                }
            }
        }
    }

    // ---- epilogue: fp16-round, streaming f32 stores (evict-first) ----
    const int r0 = bm * BM + wm * 32 + (lane >> 2);
    const int c0 = bn * BN + wn * 64 + 2 * (lane & 3);
#pragma unroll
    for (int mi = 0; mi < 2; mi++) {
#pragma unroll
        for (int ni = 0; ni < 8; ni++) {
            int r = r0 + mi * 16;
            int c = c0 + ni * 8;
            stcs2(C + (size_t)r * OUTD + c,
                  __half2float(__float2half(acc[mi][ni][0])),
                  __half2float(__float2half(acc[mi][ni][1])));
            stcs2(C + (size_t)(r + 8) * OUTD + c,
                  __half2float(__float2half(acc[mi][ni][2])),
                  __half2float(__float2half(acc[mi][ni][3])));
        }
    }
}

// ---------------------------------------------------------------------------
extern "C" void kernel_launch(void* const* d_in, const int* in_sizes, int n_in,
                              void* d_out, int out_size)
{
    const float* x      = (const float*)d_in[0];
    const int*   packed = (const int*)  d_in[1];
    const int*   am1    = (const int*)  d_in[2];
    const float* c1     = (const float*)d_in[3];
    const float* o1     = (const float*)d_in[4];
    const float* am2    = (const float*)d_in[5];
    const float* c2     = (const float*)d_in[6];
    float* out = (float*)d_out;

    prep_kernel<<<XBLK + DQBLK, 256>>>(x, packed, am1, c1, o1, am2, c2);

    cudaFuncSetAttribute(gemm_kernel,
                         cudaFuncAttributeMaxDynamicSharedMemorySize, SMEM_TOTAL);
    gemm_kernel<<<dim3(OUTD / BN, BDIM / BM), 256, SMEM_TOTAL>>>(out);
}